// round 7
// baseline (speedup 1.0000x reference)
#include <cuda_runtime.h>
#include <cuda_bf16.h>
#include <mma.h>
#include <cstdint>

using namespace nvcuda;

// ---------------------------------------------------------------------------
// C[16384,768](fp32) = A[16384,6144] @ W[768,6144]^T
//
// KEY FINDING (R4-R6): the harness stores BOTH inputs as FLOAT32 (bf16 values
// upcast to fp32 — reading them as bf16 yields 0.0 at even indices and the
// true value at odd indices, giving the observed rel_err = sqrt(1.5) for any
// otherwise-correct GEMM). So: read fp32, convert losslessly to bf16 scratch
// once, then run the pipelined wmma bf16 GEMM on the scratch.
//
//   GEMM: CTA tile 128x256, KC=64, 2-stage cp.async double buffer, padded
//   smem rows (72 elems), 512 threads = 4x4 warps, warp tile 32x64.
// ---------------------------------------------------------------------------

#define HIDDEN 6144
#define NTOK   16384
#define NEXP   768

#define TM 128
#define TN 256
#define KC 64
#define KT (HIDDEN / KC)           // 96
#define THREADS 512

#define ROWB (HIDDEN * 2)          // bf16 scratch row stride in bytes

#define LDS_ 72                    // padded smem row stride (elements)
#define LDSB (LDS_ * 2)            // 144 B

#define A_STAGE_B (TM * LDSB)      // 18432 B
#define B_STAGE_B (TN * LDSB)      // 36864 B
#define STAGE_B (A_STAGE_B + B_STAGE_B)   // 55296 B
#define SMEM_TOTAL (2 * STAGE_B)   // 110592 B

// Static scratch (allocation-free): bf16 copies of the fp32 inputs.
__device__ __nv_bfloat16 g_Abf[(size_t)NTOK * HIDDEN];   // ~201 MB
__device__ __nv_bfloat16 g_Wbf[(size_t)NEXP * HIDDEN];   // ~9.4 MB

// ---------------- fp32 -> bf16 conversion (lossless here) ------------------
__global__ void __launch_bounds__(256)
convert_kernel(const float* __restrict__ src, __nv_bfloat16* __restrict__ dst,
               int n4) {
    int i = blockIdx.x * blockDim.x + threadIdx.x;
    if (i < n4) {
        float4 v = reinterpret_cast<const float4*>(src)[i];
        __nv_bfloat162 lo = __floats2bfloat162_rn(v.x, v.y);
        __nv_bfloat162 hi = __floats2bfloat162_rn(v.z, v.w);
        reinterpret_cast<__nv_bfloat162*>(dst)[2 * i]     = lo;
        reinterpret_cast<__nv_bfloat162*>(dst)[2 * i + 1] = hi;
    }
}

// ------------------------------- GEMM --------------------------------------
__device__ __forceinline__ uint32_t s2u(const void* p) {
    return (uint32_t)__cvta_generic_to_shared(p);
}

__device__ __forceinline__ void cp16(uint32_t s, const void* g) {
    asm volatile("cp.async.cg.shared.global [%0], [%1], 16;" :: "r"(s), "l"(g));
}

__device__ __forceinline__ void load_stage(const char* gA, const char* gB,
                                           uint32_t sA, uint32_t sB, int tid) {
    #pragma unroll
    for (int i = 0; i < (TM * 8) / THREADS; i++) {       // 2 chunks
        int chunk = tid + i * THREADS;
        int row = chunk >> 3;
        int c = (chunk & 7) * 16;
        cp16(sA + (uint32_t)(row * LDSB + c), gA + (size_t)row * ROWB + c);
    }
    #pragma unroll
    for (int i = 0; i < (TN * 8) / THREADS; i++) {       // 4 chunks
        int chunk = tid + i * THREADS;
        int row = chunk >> 3;
        int c = (chunk & 7) * 16;
        cp16(sB + (uint32_t)(row * LDSB + c), gB + (size_t)row * ROWB + c);
    }
}

__global__ void __launch_bounds__(THREADS, 1)
router_gemm_kernel(float* __restrict__ C) {
    extern __shared__ char smem[];
    const int tid = threadIdx.x;
    const int wid = tid >> 5;

    const int wm = wid & 3;        // warp row: 32 M-rows each
    const int wn = wid >> 2;       // warp col: 64 N-cols each

    const int n0 = blockIdx.x * TN;
    const int m0 = blockIdx.y * TM;

    const char* gA0 = (const char*)(g_Abf + (size_t)m0 * HIDDEN);
    const char* gB0 = (const char*)(g_Wbf + (size_t)n0 * HIDDEN);

    __nv_bfloat16* pA[2];
    __nv_bfloat16* pB[2];
    uint32_t uA[2], uB[2];
    #pragma unroll
    for (int s = 0; s < 2; s++) {
        char* base = smem + s * STAGE_B;
        pA[s] = (__nv_bfloat16*)base;
        pB[s] = (__nv_bfloat16*)(base + A_STAGE_B);
        uA[s] = s2u(base);
        uB[s] = s2u(base + A_STAGE_B);
    }

    wmma::fragment<wmma::accumulator, 16, 16, 16, float> acc[2][4];
    #pragma unroll
    for (int mi = 0; mi < 2; mi++)
        #pragma unroll
        for (int ni = 0; ni < 4; ni++)
            wmma::fill_fragment(acc[mi][ni], 0.0f);

    load_stage(gA0, gB0, uA[0], uB[0], tid);
    asm volatile("cp.async.commit_group;" ::: "memory");

    for (int kt = 0; kt < KT; kt++) {
        const int cur = kt & 1;
        if (kt + 1 < KT) {
            const int nxt = (kt + 1) & 1;
            load_stage(gA0 + (size_t)(kt + 1) * (KC * 2),
                       gB0 + (size_t)(kt + 1) * (KC * 2),
                       uA[nxt], uB[nxt], tid);
            asm volatile("cp.async.commit_group;" ::: "memory");
            asm volatile("cp.async.wait_group 1;" ::: "memory");
        } else {
            asm volatile("cp.async.wait_group 0;" ::: "memory");
        }
        __syncthreads();

        #pragma unroll
        for (int ks = 0; ks < KC / 16; ks++) {
            wmma::fragment<wmma::matrix_a, 16, 16, 16, __nv_bfloat16,
                           wmma::row_major> fa[2];
            #pragma unroll
            for (int mi = 0; mi < 2; mi++)
                wmma::load_matrix_sync(
                    fa[mi], pA[cur] + (wm * 32 + mi * 16) * LDS_ + ks * 16, LDS_);

            wmma::fragment<wmma::matrix_b, 16, 16, 16, __nv_bfloat16,
                           wmma::col_major> fb;
            #pragma unroll
            for (int ni = 0; ni < 4; ni++) {
                wmma::load_matrix_sync(
                    fb, pB[cur] + (wn * 64 + ni * 16) * LDS_ + ks * 16, LDS_);
                #pragma unroll
                for (int mi = 0; mi < 2; mi++)
                    wmma::mma_sync(acc[mi][ni], fa[mi], fb, acc[mi][ni]);
            }
        }
        __syncthreads();
    }

    #pragma unroll
    for (int mi = 0; mi < 2; mi++) {
        int row0 = m0 + wm * 32 + mi * 16;
        #pragma unroll
        for (int ni = 0; ni < 4; ni++) {
            int col0 = n0 + wn * 64 + ni * 16;
            wmma::store_matrix_sync(C + (size_t)row0 * NEXP + col0,
                                    acc[mi][ni], NEXP, wmma::mem_row_major);
        }
    }
}

extern "C" void kernel_launch(void* const* d_in, const int* in_sizes, int n_in,
                              void* d_out, int out_size) {
    // Inputs are FLOAT32 (bf16 values upcast by the harness).
    const int nA = NTOK * HIDDEN;
    const float* Af;
    const float* Wf;
    if (in_sizes[0] == nA) {
        Af = (const float*)d_in[0];
        Wf = (const float*)d_in[1];
    } else {
        Af = (const float*)d_in[1];
        Wf = (const float*)d_in[0];
    }
    float* C = (float*)d_out;

    __nv_bfloat16* Abf = nullptr;
    __nv_bfloat16* Wbf = nullptr;
    cudaGetSymbolAddress((void**)&Abf, g_Abf);
    cudaGetSymbolAddress((void**)&Wbf, g_Wbf);

    const int nA4 = (NTOK * HIDDEN) / 4;      // 25165824
    const int nW4 = (NEXP * HIDDEN) / 4;      // 1179648
    convert_kernel<<<(nA4 + 255) / 256, 256>>>(Af, Abf, nA4);
    convert_kernel<<<(nW4 + 255) / 256, 256>>>(Wf, Wbf, nW4);

    cudaFuncSetAttribute(router_gemm_kernel,
                         cudaFuncAttributeMaxDynamicSharedMemorySize, SMEM_TOTAL);
    dim3 grid(NEXP / TN, NTOK / TM);   // (3, 128)
    router_gemm_kernel<<<grid, THREADS, SMEM_TOTAL>>>(C);
}

// round 13
// speedup vs baseline: 1.4562x; 1.4562x over previous
#include <cuda_runtime.h>
#include <cuda_bf16.h>
#include <cstdint>

// ---------------------------------------------------------------------------
// C[16384,768](fp32) = A[16384,6144] @ W[768,6144]^T
//
// Harness stores both inputs as FP32 (bf16 values upcast). Pipeline:
//   1) convert fp32 -> bf16 scratch (lossless), near-HBM-bound (~100us)
//   2) GEMM: hand ldmatrix + mma.sync.m16n8k16 bf16 (wiring validated in
//      R4-R6: identical outputs to wmma), 4-stage cp.async pipeline, SW128
//      swizzled smem, CTA tile 128x256, 512 threads = 4x4 warps, warp 32x64.
// ---------------------------------------------------------------------------

#define HIDDEN 6144
#define NTOK   16384
#define NEXP   768

#define TM 128
#define TN 256
#define KC 64
#define KT (HIDDEN / KC)          // 96
#define STAGES 4
#define THREADS 512

#define ROWB (HIDDEN * 2)         // bf16 scratch row stride (bytes)

#define A_BYTES (TM * 128)        // 16 KB per stage
#define B_BYTES (TN * 128)        // 32 KB per stage
#define STAGE_BYTES (A_BYTES + B_BYTES)        // 48 KB
#define SMEM_TOTAL (STAGES * STAGE_BYTES)      // 196608 B

// Static scratch (allocation-free): bf16 copies of the fp32 inputs.
__device__ __nv_bfloat16 g_Abf[(size_t)NTOK * HIDDEN];   // ~201 MB
__device__ __nv_bfloat16 g_Wbf[(size_t)NEXP * HIDDEN];   // ~9.4 MB

// ---------------- fp32 -> bf16 conversion (lossless here) ------------------
__global__ void __launch_bounds__(256)
convert_kernel(const float* __restrict__ src, __nv_bfloat16* __restrict__ dst,
               int n4) {
    int i = blockIdx.x * blockDim.x + threadIdx.x;
    if (i < n4) {
        float4 v = reinterpret_cast<const float4*>(src)[i];
        __nv_bfloat162 lo = __floats2bfloat162_rn(v.x, v.y);
        __nv_bfloat162 hi = __floats2bfloat162_rn(v.z, v.w);
        reinterpret_cast<__nv_bfloat162*>(dst)[2 * i]     = lo;
        reinterpret_cast<__nv_bfloat162*>(dst)[2 * i + 1] = hi;
    }
}

// ------------------------------- GEMM --------------------------------------
__device__ __forceinline__ uint32_t s2u(const void* p) {
    return (uint32_t)__cvta_generic_to_shared(p);
}

__device__ __forceinline__ void cp16(uint32_t s, const void* g) {
    asm volatile("cp.async.cg.shared.global [%0], [%1], 16;" :: "r"(s), "l"(g));
}

__device__ __forceinline__ uint32_t sw128(uint32_t o) {
    return o ^ ((o >> 3) & 0x70);
}

__device__ __forceinline__ void ldsm_x4(uint32_t& r0, uint32_t& r1,
                                        uint32_t& r2, uint32_t& r3, uint32_t addr) {
    asm volatile("ldmatrix.sync.aligned.m8n8.x4.shared.b16 {%0,%1,%2,%3}, [%4];"
                 : "=r"(r0), "=r"(r1), "=r"(r2), "=r"(r3) : "r"(addr));
}

__device__ __forceinline__ void mma16816(float* d, const uint32_t* a, const uint32_t* b) {
    asm volatile(
        "mma.sync.aligned.m16n8k16.row.col.f32.bf16.bf16.f32 "
        "{%0,%1,%2,%3}, {%4,%5,%6,%7}, {%8,%9}, {%0,%1,%2,%3};"
        : "+f"(d[0]), "+f"(d[1]), "+f"(d[2]), "+f"(d[3])
        : "r"(a[0]), "r"(a[1]), "r"(a[2]), "r"(a[3]), "r"(b[0]), "r"(b[1]));
}

// Load one stage: A tile TM x KC, B tile TN x KC, K-major 128B rows, swizzled.
__device__ __forceinline__ void load_stage(const char* gA, const char* gB,
                                           uint32_t sA, uint32_t sB, int tid) {
    #pragma unroll
    for (int i = 0; i < (A_BYTES / 16) / THREADS; i++) {      // 2 chunks
        int chunk = tid + i * THREADS;
        int row = chunk >> 3;
        int c = (chunk & 7) * 16;
        cp16(sA + sw128((uint32_t)(row * 128 + c)), gA + (size_t)row * ROWB + c);
    }
    #pragma unroll
    for (int i = 0; i < (B_BYTES / 16) / THREADS; i++) {      // 4 chunks
        int chunk = tid + i * THREADS;
        int row = chunk >> 3;
        int c = (chunk & 7) * 16;
        cp16(sB + sw128((uint32_t)(row * 128 + c)), gB + (size_t)row * ROWB + c);
    }
}

__global__ void __launch_bounds__(THREADS, 1)
router_gemm_kernel(float* __restrict__ C) {
    extern __shared__ char smem[];
    const uint32_t sbase = s2u(smem);
    const int tid = threadIdx.x;
    const int wid = tid >> 5;
    const int lid = tid & 31;

    const int wm = wid & 3;        // warp row (0..3): 32 M-rows each
    const int wn = wid >> 2;       // warp col (0..3): 64 N-cols each

    const int n0 = blockIdx.x * TN;    // 3 N-tiles adjacent per M-tile
    const int m0 = blockIdx.y * TM;

    const char* gA0 = (const char*)(g_Abf + (size_t)m0 * HIDDEN);
    const char* gB0 = (const char*)(g_Wbf + (size_t)n0 * HIDDEN);

    // Per-thread ldmatrix row/col offsets (within CTA tile, pre-swizzle).
    const int a_row = wm * 32 + (lid & 15);        // + mi*16
    const int a_kb  = (lid >> 4) * 16;             // k half (bytes)
    const int b_row = wn * 64 + (lid & 7) + ((lid >> 4) & 1) * 8;  // + ni2*16
    const int b_kb  = ((lid >> 3) & 1) * 16;

    float acc[2][8][4];
    #pragma unroll
    for (int mi = 0; mi < 2; mi++)
        #pragma unroll
        for (int ni = 0; ni < 8; ni++)
            #pragma unroll
            for (int j = 0; j < 4; j++) acc[mi][ni][j] = 0.0f;

    // Prologue: stages 0..STAGES-2
    #pragma unroll
    for (int s = 0; s < STAGES - 1; s++) {
        uint32_t sA = sbase + s * STAGE_BYTES;
        load_stage(gA0 + s * (KC * 2), gB0 + s * (KC * 2), sA, sA + A_BYTES, tid);
        asm volatile("cp.async.commit_group;" ::: "memory");
    }

    for (int kt = 0; kt < KT; kt++) {
        // stage kt data resident (3 groups pending -> wait to <=2)
        asm volatile("cp.async.wait_group %0;" :: "n"(STAGES - 2) : "memory");
        __syncthreads();

        // issue loads for stage kt+STAGES-1 into slot (kt-1)%STAGES (free now)
        int kl = kt + STAGES - 1;
        if (kl < KT) {
            uint32_t sA = sbase + (kl % STAGES) * STAGE_BYTES;
            load_stage(gA0 + kl * (KC * 2), gB0 + kl * (KC * 2), sA, sA + A_BYTES, tid);
        }
        asm volatile("cp.async.commit_group;" ::: "memory");

        // compute stage kt
        const uint32_t sA = sbase + (kt % STAGES) * STAGE_BYTES;
        const uint32_t sB = sA + A_BYTES;

        #pragma unroll
        for (int ks = 0; ks < KC / 16; ks++) {
            uint32_t a[2][4];
            #pragma unroll
            for (int mi = 0; mi < 2; mi++) {
                uint32_t addr = sA + sw128((uint32_t)((a_row + mi * 16) * 128
                                                      + ks * 32 + a_kb));
                ldsm_x4(a[mi][0], a[mi][1], a[mi][2], a[mi][3], addr);
            }
            uint32_t b[8][2];
            #pragma unroll
            for (int ni2 = 0; ni2 < 4; ni2++) {
                uint32_t addr = sB + sw128((uint32_t)((b_row + ni2 * 16) * 128
                                                      + ks * 32 + b_kb));
                ldsm_x4(b[ni2 * 2][0], b[ni2 * 2][1],
                        b[ni2 * 2 + 1][0], b[ni2 * 2 + 1][1], addr);
            }
            #pragma unroll
            for (int mi = 0; mi < 2; mi++)
                #pragma unroll
                for (int ni = 0; ni < 8; ni++)
                    mma16816(acc[mi][ni], a[mi], b[ni]);
        }
    }

    // Epilogue: direct fp32 stores (layout validated via R4<->wmma identity).
    {
        const int tr = lid >> 2;          // 0..7
        const int tc = (lid & 3) * 2;     // 0,2,4,6
        #pragma unroll
        for (int mi = 0; mi < 2; mi++) {
            int row_lo = m0 + wm * 32 + mi * 16 + tr;
            float* out_lo = C + (size_t)row_lo * NEXP + n0 + wn * 64 + tc;
            float* out_hi = out_lo + 8 * NEXP;
            #pragma unroll
            for (int ni = 0; ni < 8; ni++) {
                *reinterpret_cast<float2*>(out_lo + ni * 8) =
                    make_float2(acc[mi][ni][0], acc[mi][ni][1]);
                *reinterpret_cast<float2*>(out_hi + ni * 8) =
                    make_float2(acc[mi][ni][2], acc[mi][ni][3]);
            }
        }
    }
}

extern "C" void kernel_launch(void* const* d_in, const int* in_sizes, int n_in,
                              void* d_out, int out_size) {
    // Inputs are FLOAT32 (bf16 values upcast by the harness).
    const int nA = NTOK * HIDDEN;
    const float* Af;
    const float* Wf;
    if (in_sizes[0] == nA) {
        Af = (const float*)d_in[0];
        Wf = (const float*)d_in[1];
    } else {
        Af = (const float*)d_in[1];
        Wf = (const float*)d_in[0];
    }
    float* C = (float*)d_out;

    __nv_bfloat16* Abf = nullptr;
    __nv_bfloat16* Wbf = nullptr;
    cudaGetSymbolAddress((void**)&Abf, g_Abf);
    cudaGetSymbolAddress((void**)&Wbf, g_Wbf);

    const int nA4 = (NTOK * HIDDEN) / 4;
    const int nW4 = (NEXP * HIDDEN) / 4;
    convert_kernel<<<(nA4 + 255) / 256, 256>>>(Af, Abf, nA4);
    convert_kernel<<<(nW4 + 255) / 256, 256>>>(Wf, Wbf, nW4);

    cudaFuncSetAttribute(router_gemm_kernel,
                         cudaFuncAttributeMaxDynamicSharedMemorySize, SMEM_TOTAL);
    dim3 grid(NEXP / TN, NTOK / TM);   // (3, 128)
    router_gemm_kernel<<<grid, THREADS, SMEM_TOTAL>>>(C);
}

// round 14
// speedup vs baseline: 1.4988x; 1.0292x over previous
#include <cuda_runtime.h>
#include <cuda_bf16.h>
#include <cstdint>

// ---------------------------------------------------------------------------
// C[16384,768](fp32) = A[16384,6144] @ W[768,6144]^T
//
// Harness stores both inputs as FP32 (bf16 values upcast). Pipeline:
//   1) ONE merged convert kernel: fp32 -> bf16 scratch for A and W
//      (lossless; HBM-bound ~100us). Merged so ncu -s 5 hits the GEMM.
//   2) GEMM: hand ldmatrix + mma.sync.m16n8k16 bf16 (wiring validated),
//      3-stage cp.async pipeline, SW128 smem, CTA tile 128x128, 256 threads
//      = 4(M)x2(N) warps, warp tile 32x64 (identical per-warp code to R13),
//      2 CTAs/SM for latency/sync-bubble overlap.
// ---------------------------------------------------------------------------

#define HIDDEN 6144
#define NTOK   16384
#define NEXP   768

#define TM 128
#define TN 128
#define KC 64
#define KT (HIDDEN / KC)          // 96
#define STAGES 3
#define THREADS 256

#define ROWB (HIDDEN * 2)         // bf16 scratch row stride (bytes)

#define A_BYTES (TM * 128)        // 16 KB per stage
#define B_BYTES (TN * 128)        // 16 KB per stage
#define STAGE_BYTES (A_BYTES + B_BYTES)        // 32 KB
#define SMEM_TOTAL (STAGES * STAGE_BYTES)      // 98304 B -> 2 CTAs/SM

// Static scratch (allocation-free): bf16 copies of the fp32 inputs.
__device__ __nv_bfloat16 g_Abf[(size_t)NTOK * HIDDEN];   // ~201 MB
__device__ __nv_bfloat16 g_Wbf[(size_t)NEXP * HIDDEN];   // ~9.4 MB

#define NA4 ((NTOK * HIDDEN) / 4)     // 25165824 float4 chunks in A
#define NW4 ((NEXP * HIDDEN) / 4)     // 1179648 in W

// -------- merged fp32 -> bf16 conversion (lossless; one launch) ------------
__global__ void __launch_bounds__(256)
convert_all_kernel(const float* __restrict__ srcA, const float* __restrict__ srcW) {
    int i = blockIdx.x * blockDim.x + threadIdx.x;
    const float* src;
    __nv_bfloat16* dst;
    int idx;
    if (i < NA4) {
        src = srcA; dst = g_Abf; idx = i;
    } else if (i < NA4 + NW4) {
        src = srcW; dst = g_Wbf; idx = i - NA4;
    } else {
        return;
    }
    float4 v = reinterpret_cast<const float4*>(src)[idx];
    __nv_bfloat162 lo = __floats2bfloat162_rn(v.x, v.y);
    __nv_bfloat162 hi = __floats2bfloat162_rn(v.z, v.w);
    reinterpret_cast<__nv_bfloat162*>(dst)[2 * idx]     = lo;
    reinterpret_cast<__nv_bfloat162*>(dst)[2 * idx + 1] = hi;
}

// ------------------------------- GEMM --------------------------------------
__device__ __forceinline__ uint32_t s2u(const void* p) {
    return (uint32_t)__cvta_generic_to_shared(p);
}

__device__ __forceinline__ void cp16(uint32_t s, const void* g) {
    asm volatile("cp.async.cg.shared.global [%0], [%1], 16;" :: "r"(s), "l"(g));
}

__device__ __forceinline__ uint32_t sw128(uint32_t o) {
    return o ^ ((o >> 3) & 0x70);
}

__device__ __forceinline__ void ldsm_x4(uint32_t& r0, uint32_t& r1,
                                        uint32_t& r2, uint32_t& r3, uint32_t addr) {
    asm volatile("ldmatrix.sync.aligned.m8n8.x4.shared.b16 {%0,%1,%2,%3}, [%4];"
                 : "=r"(r0), "=r"(r1), "=r"(r2), "=r"(r3) : "r"(addr));
}

__device__ __forceinline__ void mma16816(float* d, const uint32_t* a, const uint32_t* b) {
    asm volatile(
        "mma.sync.aligned.m16n8k16.row.col.f32.bf16.bf16.f32 "
        "{%0,%1,%2,%3}, {%4,%5,%6,%7}, {%8,%9}, {%0,%1,%2,%3};"
        : "+f"(d[0]), "+f"(d[1]), "+f"(d[2]), "+f"(d[3])
        : "r"(a[0]), "r"(a[1]), "r"(a[2]), "r"(a[3]), "r"(b[0]), "r"(b[1]));
}

// Load one stage: A tile TM x KC, B tile TN x KC, K-major 128B rows, swizzled.
__device__ __forceinline__ void load_stage(const char* gA, const char* gB,
                                           uint32_t sA, uint32_t sB, int tid) {
    #pragma unroll
    for (int i = 0; i < (A_BYTES / 16) / THREADS; i++) {      // 4 chunks
        int chunk = tid + i * THREADS;
        int row = chunk >> 3;
        int c = (chunk & 7) * 16;
        cp16(sA + sw128((uint32_t)(row * 128 + c)), gA + (size_t)row * ROWB + c);
    }
    #pragma unroll
    for (int i = 0; i < (B_BYTES / 16) / THREADS; i++) {      // 4 chunks
        int chunk = tid + i * THREADS;
        int row = chunk >> 3;
        int c = (chunk & 7) * 16;
        cp16(sB + sw128((uint32_t)(row * 128 + c)), gB + (size_t)row * ROWB + c);
    }
}

__global__ void __launch_bounds__(THREADS, 2)
router_gemm_kernel(float* __restrict__ C) {
    extern __shared__ char smem[];
    const uint32_t sbase = s2u(smem);
    const int tid = threadIdx.x;
    const int wid = tid >> 5;
    const int lid = tid & 31;

    const int wm = wid & 3;        // warp row (0..3): 32 M-rows each
    const int wn = wid >> 2;       // warp col (0..1): 64 N-cols each

    const int n0 = blockIdx.x * TN;    // n-fast: 6 adjacent CTAs share A tile
    const int m0 = blockIdx.y * TM;

    const char* gA0 = (const char*)(g_Abf + (size_t)m0 * HIDDEN);
    const char* gB0 = (const char*)(g_Wbf + (size_t)n0 * HIDDEN);

    // Per-thread ldmatrix row/col offsets (within CTA tile, pre-swizzle).
    const int a_row = wm * 32 + (lid & 15);        // + mi*16
    const int a_kb  = (lid >> 4) * 16;             // k half (bytes)
    const int b_row = wn * 64 + (lid & 7) + ((lid >> 4) & 1) * 8;  // + ni2*16
    const int b_kb  = ((lid >> 3) & 1) * 16;

    float acc[2][8][4];
    #pragma unroll
    for (int mi = 0; mi < 2; mi++)
        #pragma unroll
        for (int ni = 0; ni < 8; ni++)
            #pragma unroll
            for (int j = 0; j < 4; j++) acc[mi][ni][j] = 0.0f;

    // Prologue: stages 0..STAGES-2
    #pragma unroll
    for (int s = 0; s < STAGES - 1; s++) {
        uint32_t sA = sbase + s * STAGE_BYTES;
        load_stage(gA0 + s * (KC * 2), gB0 + s * (KC * 2), sA, sA + A_BYTES, tid);
        asm volatile("cp.async.commit_group;" ::: "memory");
    }

    for (int kt = 0; kt < KT; kt++) {
        // stage kt data resident (2 groups pending -> wait to <=1)
        asm volatile("cp.async.wait_group %0;" :: "n"(STAGES - 2) : "memory");
        __syncthreads();

        // issue loads for stage kt+STAGES-1 into slot (kt-1)%STAGES (free now)
        int kl = kt + STAGES - 1;
        if (kl < KT) {
            uint32_t sA = sbase + (kl % STAGES) * STAGE_BYTES;
            load_stage(gA0 + kl * (KC * 2), gB0 + kl * (KC * 2), sA, sA + A_BYTES, tid);
        }
        asm volatile("cp.async.commit_group;" ::: "memory");

        // compute stage kt
        const uint32_t sA = sbase + (kt % STAGES) * STAGE_BYTES;
        const uint32_t sB = sA + A_BYTES;

        #pragma unroll
        for (int ks = 0; ks < KC / 16; ks++) {
            uint32_t a[2][4];
            #pragma unroll
            for (int mi = 0; mi < 2; mi++) {
                uint32_t addr = sA + sw128((uint32_t)((a_row + mi * 16) * 128
                                                      + ks * 32 + a_kb));
                ldsm_x4(a[mi][0], a[mi][1], a[mi][2], a[mi][3], addr);
            }
            uint32_t b[8][2];
            #pragma unroll
            for (int ni2 = 0; ni2 < 4; ni2++) {
                uint32_t addr = sB + sw128((uint32_t)((b_row + ni2 * 16) * 128
                                                      + ks * 32 + b_kb));
                ldsm_x4(b[ni2 * 2][0], b[ni2 * 2][1],
                        b[ni2 * 2 + 1][0], b[ni2 * 2 + 1][1], addr);
            }
            #pragma unroll
            for (int mi = 0; mi < 2; mi++)
                #pragma unroll
                for (int ni = 0; ni < 8; ni++)
                    mma16816(acc[mi][ni], a[mi], b[ni]);
        }
    }

    // Epilogue: direct fp32 stores (layout validated via R4<->wmma identity).
    {
        const int tr = lid >> 2;          // 0..7
        const int tc = (lid & 3) * 2;     // 0,2,4,6
        #pragma unroll
        for (int mi = 0; mi < 2; mi++) {
            int row_lo = m0 + wm * 32 + mi * 16 + tr;
            float* out_lo = C + (size_t)row_lo * NEXP + n0 + wn * 64 + tc;
            float* out_hi = out_lo + 8 * NEXP;
            #pragma unroll
            for (int ni = 0; ni < 8; ni++) {
                *reinterpret_cast<float2*>(out_lo + ni * 8) =
                    make_float2(acc[mi][ni][0], acc[mi][ni][1]);
                *reinterpret_cast<float2*>(out_hi + ni * 8) =
                    make_float2(acc[mi][ni][2], acc[mi][ni][3]);
            }
        }
    }
}

extern "C" void kernel_launch(void* const* d_in, const int* in_sizes, int n_in,
                              void* d_out, int out_size) {
    // Inputs are FLOAT32 (bf16 values upcast by the harness).
    const int nA = NTOK * HIDDEN;
    const float* Af;
    const float* Wf;
    if (in_sizes[0] == nA) {
        Af = (const float*)d_in[0];
        Wf = (const float*)d_in[1];
    } else {
        Af = (const float*)d_in[1];
        Wf = (const float*)d_in[0];
    }
    float* C = (float*)d_out;

    const int total4 = NA4 + NW4;
    convert_all_kernel<<<(total4 + 255) / 256, 256>>>(Af, Wf);

    cudaFuncSetAttribute(router_gemm_kernel,
                         cudaFuncAttributeMaxDynamicSharedMemorySize, SMEM_TOTAL);
    dim3 grid(NEXP / TN, NTOK / TM);   // (6, 128)
    router_gemm_kernel<<<grid, THREADS, SMEM_TOTAL>>>(C);
}